// round 6
// baseline (speedup 1.0000x reference)
#include <cuda_runtime.h>
#include <cuda_bf16.h>
#include <cstdint>

// Problem constants
static constexpr int T_ = 2048;
static constexpr int B_ = 16;
static constexpr int D_ = 1024;
static constexpr int M_ = T_ * B_;    // 32768
static constexpr int N_ = 3 * D_;     // 3072
static constexpr int K_ = D_;         // 1024
static constexpr int K3_ = 3 * K_;    // 3072 packed split-K
static constexpr float EPS_ = 1e-5f;

// GEMM tiling (mma.sync path — tcgen05 unavailable: harness emits compute_103 PTX)
static constexpr int BM = 128;
static constexpr int BN = 256;
static constexpr int BK = 32;
static constexpr int KT = K3_ / BK;       // 96 K-steps
static constexpr int STAGES = 4;
static constexpr int APAD = 8, BPAD = 8;
static constexpr int A_BYTES = BM * (BK + APAD) * 2;   // 10240
static constexpr int B_BYTES = BK * (BN + BPAD) * 2;   // 16896
static constexpr int STAGE_BYTES = A_BYTES + B_BYTES;  // 27136
static constexpr int DSMEM_BYTES = STAGES * STAGE_BYTES; // 108544

// Scratch (__device__ globals; no runtime allocation allowed)
__device__ __nv_bfloat16 g_A2[(size_t)M_ * K3_];   // rows x [hi | hi | lo]
__device__ __nv_bfloat16 g_B2[(size_t)K3_ * N_];   // K'-major x N: [Whi | Wlo | Whi]
__device__ float g_pre[(size_t)M_ * N_];
__device__ float g_post[(size_t)M_ * N_];

// ---------------------------------------------------------------------------
// PTX helpers
// ---------------------------------------------------------------------------
#define CP_ASYNC16(dst, src) \
    asm volatile("cp.async.cg.shared.global [%0], [%1], 16;\n" :: "r"(dst), "l"(src))
#define CP_COMMIT() asm volatile("cp.async.commit_group;\n" ::)
#define CP_WAIT(n)  asm volatile("cp.async.wait_group %0;\n" :: "n"(n))

#define LDSM4(R0, R1, R2, R3, addr)                                                \
    asm volatile("ldmatrix.sync.aligned.m8n8.x4.shared.b16 {%0,%1,%2,%3}, [%4];\n" \
                 : "=r"(R0), "=r"(R1), "=r"(R2), "=r"(R3) : "r"(addr))
#define LDSM4T(R0, R1, R2, R3, addr)                                               \
    asm volatile("ldmatrix.sync.aligned.m8n8.x4.trans.shared.b16 {%0,%1,%2,%3}, [%4];\n" \
                 : "=r"(R0), "=r"(R1), "=r"(R2), "=r"(R3) : "r"(addr))
#define MMA16816(C, A0, A1, A2r, A3, B0, B1)                                 \
    asm volatile("mma.sync.aligned.m16n8k16.row.col.f32.bf16.bf16.f32 "      \
                 "{%0,%1,%2,%3},{%4,%5,%6,%7},{%8,%9},{%0,%1,%2,%3};\n"      \
                 : "+f"(C[0]), "+f"(C[1]), "+f"(C[2]), "+f"(C[3])            \
                 : "r"(A0), "r"(A1), "r"(A2r), "r"(A3), "r"(B0), "r"(B1))

// ---------------------------------------------------------------------------
// Kernel 0a: split input fp32 -> bf16 [hi | hi | lo] along K'
// ---------------------------------------------------------------------------
__global__ __launch_bounds__(256) void convert_A_kernel(const float* __restrict__ in) {
    size_t i = (size_t)blockIdx.x * blockDim.x + threadIdx.x;
    if (i >= (size_t)M_ * K_) return;
    int m = (int)(i >> 10);
    int k = (int)(i & (K_ - 1));
    float x = in[i];
    __nv_bfloat16 hi = __float2bfloat16(x);
    __nv_bfloat16 lo = __float2bfloat16(x - __bfloat162float(hi));
    size_t base = (size_t)m * K3_;
    g_A2[base + k]          = hi;
    g_A2[base + K_ + k]     = hi;
    g_A2[base + 2 * K_ + k] = lo;
}

// Kernel 0b: split W fp32 -> bf16 [hi | lo | hi] stacked along K' (row-major K'xN)
__global__ __launch_bounds__(256) void convert_W_kernel(const float* __restrict__ Wp) {
    size_t i = (size_t)blockIdx.x * blockDim.x + threadIdx.x;
    if (i >= (size_t)K_ * N_) return;
    int k = (int)(i / N_);
    int n = (int)(i % N_);
    float x = Wp[i];
    __nv_bfloat16 hi = __float2bfloat16(x);
    __nv_bfloat16 lo = __float2bfloat16(x - __bfloat162float(hi));
    g_B2[(size_t)k * N_ + n]            = hi;
    g_B2[(size_t)(K_ + k) * N_ + n]     = lo;
    g_B2[(size_t)(2 * K_ + k) * N_ + n] = hi;
}

// ---------------------------------------------------------------------------
// Kernel 1: bf16 mma.sync GEMM  g_pre = A2(M x K') * B2(K' x N), fp32 accum.
// 128x256x32 CTA tile, 8 warps (2x4) of 64x64, 4-stage cp.async pipeline.
// ---------------------------------------------------------------------------
__global__ __launch_bounds__(256, 1) void mma_gemm_kernel() {
    extern __shared__ char dsm[];

    const int tid  = threadIdx.x;
    const int lane = tid & 31;
    const int warp = tid >> 5;
    const int wm = warp & 1, wn = warp >> 1;          // 2 x 4 warp grid
    const int m0 = wm * 64, n0 = wn * 64;
    const int bx = blockIdx.x, by = blockIdx.y;

    const __nv_bfloat16* Ag = g_A2 + (size_t)by * BM * K3_;
    const __nv_bfloat16* Bg = g_B2 + (size_t)bx * BN;

    const uint32_t sbase = (uint32_t)__cvta_generic_to_shared(dsm);

    // cooperative-load coords
    const int a_r0 = tid >> 2, a_c0 = (tid & 3) * 8;      // 2 chunks: rows +0, +64
    const int b_r0 = tid >> 5, b_c0 = (tid & 31) * 8;     // 4 chunks: rows +0,8,16,24

    float acc[4][8][4];
#pragma unroll
    for (int i = 0; i < 4; i++)
#pragma unroll
        for (int j = 0; j < 8; j++)
#pragma unroll
            for (int v = 0; v < 4; v++) acc[i][j][v] = 0.f;

    auto load_stage = [&](int kt) {
        const int s = kt & (STAGES - 1);
        const int k0 = kt * BK;
        const uint32_t ab = sbase + s * STAGE_BYTES;
        const uint32_t bb = ab + A_BYTES;
#pragma unroll
        for (int i = 0; i < 2; i++) {
            int r = a_r0 + i * 64;
            CP_ASYNC16(ab + (r * (BK + APAD) + a_c0) * 2,
                       Ag + (size_t)r * K3_ + k0 + a_c0);
        }
#pragma unroll
        for (int i = 0; i < 4; i++) {
            int r = b_r0 + i * 8;
            CP_ASYNC16(bb + (r * (BN + BPAD) + b_c0) * 2,
                       Bg + (size_t)(k0 + r) * N_ + b_c0);
        }
    };

    // prefetch STAGES-1 stages
#pragma unroll
    for (int kt = 0; kt < STAGES - 1; kt++) { load_stage(kt); CP_COMMIT(); }

    const int lrow = lane & 15;
    const int lsel = lane >> 4;

    for (int kt = 0; kt < KT; kt++) {
        CP_WAIT(STAGES - 2);
        __syncthreads();
        if (kt + STAGES - 1 < KT) load_stage(kt + STAGES - 1);
        CP_COMMIT();

        const int s = kt & (STAGES - 1);
        const uint32_t ab = sbase + s * STAGE_BYTES;
        const uint32_t bb = ab + A_BYTES;

#pragma unroll
        for (int kk = 0; kk < BK; kk += 16) {
            uint32_t a[4][4];
#pragma unroll
            for (int im = 0; im < 4; im++) {
                uint32_t addr = ab + ((m0 + im * 16 + lrow) * (BK + APAD) + kk + 8 * lsel) * 2;
                LDSM4(a[im][0], a[im][1], a[im][2], a[im][3], addr);
            }
#pragma unroll
            for (int jn = 0; jn < 4; jn++) {
                uint32_t b0, b1, b2, b3;
                uint32_t addr = bb + ((kk + lrow) * (BN + BPAD) + n0 + jn * 16 + 8 * lsel) * 2;
                LDSM4T(b0, b1, b2, b3, addr);
#pragma unroll
                for (int im = 0; im < 4; im++) {
                    MMA16816(acc[im][2 * jn],     a[im][0], a[im][1], a[im][2], a[im][3], b0, b1);
                    MMA16816(acc[im][2 * jn + 1], a[im][0], a[im][1], a[im][2], a[im][3], b2, b3);
                }
            }
        }
    }

    // Epilogue: fp32 -> g_pre
    const int gid = lane >> 2, tig = lane & 3;
#pragma unroll
    for (int im = 0; im < 4; im++) {
#pragma unroll
        for (int jn = 0; jn < 8; jn++) {
            int r = by * BM + m0 + im * 16 + gid;
            int c = bx * BN + n0 + jn * 8 + 2 * tig;
            float* p = g_pre + (size_t)r * N_ + c;
            *(float2*)p            = make_float2(acc[im][jn][0], acc[im][jn][1]);
            *(float2*)(p + 8 * N_) = make_float2(acc[im][jn][2], acc[im][jn][3]);
        }
    }
}

// ---------------------------------------------------------------------------
// Kernel 2: LayerNorm over N=3072 + affine + sigmoid on thirds 0 and 2.
// ---------------------------------------------------------------------------
__device__ __forceinline__ float sigmoidf_(float y) {
    return 1.f / (1.f + __expf(-y));
}

__global__ __launch_bounds__(256) void ln_act_kernel(const float* __restrict__ gamma,
                                                     const float* __restrict__ beta) {
    const int r = blockIdx.x;
    const float* row = g_pre + (size_t)r * N_;
    float* orow = g_post + (size_t)r * N_;

    float sum = 0.f, sumsq = 0.f;
    for (int i = threadIdx.x; i < N_ / 4; i += 256) {
        float4 v = ((const float4*)row)[i];
        sum += v.x + v.y + v.z + v.w;
        sumsq += v.x * v.x + v.y * v.y + v.z * v.z + v.w * v.w;
    }
    __shared__ float s1[32], s2[32];
#pragma unroll
    for (int o = 16; o; o >>= 1) {
        sum += __shfl_down_sync(~0u, sum, o);
        sumsq += __shfl_down_sync(~0u, sumsq, o);
    }
    int w = threadIdx.x >> 5, l = threadIdx.x & 31;
    if (!l) { s1[w] = sum; s2[w] = sumsq; }
    __syncthreads();
    if (w == 0) {
        sum = (l < 8) ? s1[l] : 0.f;
        sumsq = (l < 8) ? s2[l] : 0.f;
#pragma unroll
        for (int o = 4; o; o >>= 1) {
            sum += __shfl_down_sync(~0u, sum, o);
            sumsq += __shfl_down_sync(~0u, sumsq, o);
        }
        if (!l) {
            float mu = sum * (1.f / N_);
            float var = sumsq * (1.f / N_) - mu * mu;
            s1[0] = mu;
            s2[0] = rsqrtf(var + EPS_);
        }
    }
    __syncthreads();
    const float mu = s1[0], inv = s2[0];

    for (int i = threadIdx.x; i < N_ / 4; i += 256) {
        float4 v = ((const float4*)row)[i];
        float4 gm = ((const float4*)gamma)[i];
        float4 bt = ((const float4*)beta)[i];
        float4 y;
        y.x = (v.x - mu) * inv * gm.x + bt.x;
        y.y = (v.y - mu) * inv * gm.y + bt.y;
        y.z = (v.z - mu) * inv * gm.z + bt.z;
        y.w = (v.w - mu) * inv * gm.w + bt.w;
        int o = i * 4;
        if (o < D_ || o >= 2 * D_) {
            y.x = sigmoidf_(y.x);
            y.y = sigmoidf_(y.y);
            y.z = sigmoidf_(y.z);
            y.w = sigmoidf_(y.w);
        }
        ((float4*)orow)[i] = y;
    }
}

// ---------------------------------------------------------------------------
// Kernel 3: linear recurrence scan (fwd c<D/2, bwd c>=D/2) + output combine.
// ---------------------------------------------------------------------------
__global__ __launch_bounds__(256) void scan_combine_kernel(const float* __restrict__ input,
                                                           float* __restrict__ out) {
    const int ch = blockIdx.x * blockDim.x + threadIdx.x;
    if (ch >= B_ * D_) return;
    const int b = ch >> 10;
    const int c = ch & (D_ - 1);

    const size_t stride3 = (size_t)B_ * N_;
    const size_t stride1 = (size_t)B_ * D_;
    const size_t base3 = (size_t)b * N_ + c;
    const size_t base1 = (size_t)b * D_ + c;

    float h = 0.f;
    if (c < D_ / 2) {
#pragma unroll 4
        for (int t = 0; t < T_; t++) {
            size_t r3 = base3 + (size_t)t * stride3;
            size_t r1 = base1 + (size_t)t * stride1;
            float g = g_post[r3];
            float x = g_post[r3 + D_];
            float hg = g_post[r3 + 2 * D_];
            float inp = input[r1];
            h = (1.f - g) * h + g * x;
            out[r1] = (1.f - hg) * h + inp * hg;
        }
    } else {
#pragma unroll 4
        for (int t = T_ - 1; t >= 0; t--) {
            size_t r3 = base3 + (size_t)t * stride3;
            size_t r1 = base1 + (size_t)t * stride1;
            float g = g_post[r3];
            float x = g_post[r3 + D_];
            float hg = g_post[r3 + 2 * D_];
            float inp = input[r1];
            h = (1.f - g) * h + g * x;
            out[r1] = (1.f - hg) * h + inp * hg;
        }
    }
}

// ---------------------------------------------------------------------------
extern "C" void kernel_launch(void* const* d_in, const int* in_sizes, int n_in,
                              void* d_out, int out_size) {
    const float* input = (const float*)d_in[0];   // (T, B, D)
    const float* W     = (const float*)d_in[1];   // (D, 3D)
    const float* gamma = (const float*)d_in[2];   // (3D,)
    const float* beta  = (const float*)d_in[3];   // (3D,)
    float* out = (float*)d_out;                   // (T, B, D)

    convert_A_kernel<<<(int)(((size_t)M_ * K_ + 255) / 256), 256>>>(input);
    convert_W_kernel<<<(int)(((size_t)K_ * N_ + 255) / 256), 256>>>(W);

    cudaFuncSetAttribute(mma_gemm_kernel, cudaFuncAttributeMaxDynamicSharedMemorySize,
                         DSMEM_BYTES);
    dim3 ggrid(N_ / BN, M_ / BM);                 // 12 x 256
    mma_gemm_kernel<<<ggrid, 256, DSMEM_BYTES>>>();

    ln_act_kernel<<<M_, 256>>>(gamma, beta);

    scan_combine_kernel<<<(B_ * D_ + 255) / 256, 256>>>(input, out);
}